// round 6
// baseline (speedup 1.0000x reference)
#include <cuda_runtime.h>
#include <cstdint>

#define SEQ   4096
#define BATCH 64
#define DIM   96
#define HID   128
#define NROWS (SEQ*BATCH)

using u64 = unsigned long long;

// ---------------- scratch (static device globals) ---------------------------
__device__ float g_zx0[(size_t)NROWS*1024 + 65536];  // [row=t*64+b][n], +1 step pad
__device__ float g_zx1[(size_t)NROWS*1024 + 65536];
__device__ float g_ys0[(size_t)NROWS*256];           // [t][b][2H]
__device__ float g_ys1[(size_t)NROWS*256];

// ---------------- helpers ----------------------------------------------------
__device__ __forceinline__ float sigm(float x)   { return 1.f/(1.f+__expf(-x)); }
__device__ __forceinline__ float tanh_s(float x) { float e=__expf(2.f*x); return 1.f-2.f/(e+1.f); }
__device__ __forceinline__ void ffma2(u64 &d, u64 a, u64 b) {
    asm volatile("fma.rn.f32x2 %0, %1, %2, %0;" : "+l"(d) : "l"(a), "l"(b));
}
__device__ __forceinline__ void lds2(u64 &a, u64 &b, uint32_t addr) {
    asm volatile("ld.shared.v2.u64 {%0,%1}, [%2];" : "=l"(a), "=l"(b) : "r"(addr));
}
__device__ __forceinline__ u64 lds1(uint32_t addr) {
    u64 a; asm volatile("ld.shared.u64 %0, [%1];" : "=l"(a) : "r"(addr)); return a;
}
__device__ __forceinline__ void unpk(float &lo, float &hi, u64 v) {
    asm volatile("mov.b64 {%0,%1}, %2;" : "=f"(lo), "=f"(hi) : "l"(v));
}
__device__ __forceinline__ uint32_t f2tf32(float x) {
    uint32_t r; asm("cvt.rna.tf32.f32 %0, %1;" : "=r"(r) : "f"(x)); return r;
}
__device__ __forceinline__ void mma_tf32(float4 &c,
    uint32_t a0, uint32_t a1, uint32_t a2, uint32_t a3,
    uint32_t b0, uint32_t b1)
{
    asm volatile("mma.sync.aligned.m16n8k8.row.col.f32.tf32.tf32.f32 "
        "{%0,%1,%2,%3}, {%4,%5,%6,%7}, {%8,%9}, {%0,%1,%2,%3};"
        : "+f"(c.x), "+f"(c.y), "+f"(c.z), "+f"(c.w)
        : "r"(a0), "r"(a1), "r"(a2), "r"(a3), "r"(b0), "r"(b1));
}

// ---------------- input-projection GEMM: tf32 tensor cores -------------------
// Z[row][n] = bias[n] + sum_k A[row][k]*W[n][k]
// CTA 128(M)x128(N), K-tile 32, 8 warps = 4(M)x2(N), warp = 32x64.
// smem k-permutation p=(k&3)*8+(k>>2): each fragment row-span is 8 contiguous
// floats -> 2 LDS.128, phase-conflict-free at pad 36. Reg double-buffered LDG.
#define GPAD 36
template<int K, int LAYER>
__global__ void __launch_bounds__(256) mma_gemm(
    const float* __restrict__ Aext,
    const float* __restrict__ Wf, const float* __restrict__ Wb,
    const float* __restrict__ bf, const float* __restrict__ bb)
{
    __shared__ uint32_t As[128*GPAD];
    __shared__ uint32_t Ws[128*GPAD];

    const float* A = (LAYER == 0) ? Aext : (const float*)g_ys0;
    float*       Z = LAYER ? g_zx1 : g_zx0;

    const int n0 = blockIdx.x * 128;
    const int m0 = blockIdx.y * 128;
    const float* W    = (n0 < 512) ? (Wf + (size_t)n0*K) : (Wb + (size_t)(n0-512)*K);
    const float* bias = (n0 < 512) ? (bf + n0) : (bb + (n0-512));

    const int tid  = threadIdx.x;
    const int wid  = tid >> 5, lane = tid & 31;
    const int wm   = wid & 3,  wn   = wid >> 2;
    const int g    = lane >> 2, t   = lane & 3;
    const int ldr  = tid >> 3, ldkq = tid & 7;   // loader row/quad

    float4 acc[2][8];
#pragma unroll
    for (int mi = 0; mi < 2; mi++)
#pragma unroll
        for (int ni = 0; ni < 8; ni++) acc[mi][ni] = make_float4(0.f,0.f,0.f,0.f);

    float4 pa[4], pw[4];
#pragma unroll
    for (int i = 0; i < 4; i++) {                 // prefetch tile 0
        int r = ldr + i*32;
        pa[i] = *(const float4*)(A + (size_t)(m0+r)*K + ldkq*4);
        pw[i] = *(const float4*)(W + (size_t)r*K    + ldkq*4);
    }

    const int NT = K / 32;
    for (int kt = 0; kt < NT; kt++) {
#pragma unroll
        for (int i = 0; i < 4; i++) {             // store permuted: p = j*8+kq
            int r = ldr + i*32;
            uint32_t* ap = &As[r*GPAD + ldkq];
            ap[0]  = f2tf32(pa[i].x); ap[8]  = f2tf32(pa[i].y);
            ap[16] = f2tf32(pa[i].z); ap[24] = f2tf32(pa[i].w);
            uint32_t* wp = &Ws[r*GPAD + ldkq];
            wp[0]  = f2tf32(pw[i].x); wp[8]  = f2tf32(pw[i].y);
            wp[16] = f2tf32(pw[i].z); wp[24] = f2tf32(pw[i].w);
        }
        __syncthreads();
        if (kt + 1 < NT) {
            int k0n = (kt+1)*32;
#pragma unroll
            for (int i = 0; i < 4; i++) {
                int r = ldr + i*32;
                pa[i] = *(const float4*)(A + (size_t)(m0+r)*K + k0n + ldkq*4);
                pw[i] = *(const float4*)(W + (size_t)r*K    + k0n + ldkq*4);
            }
        }
        // fragment spans: row X, words t*8 .. t*8+7
        uint32_t ar0[2][8], ar8[2][8];
#pragma unroll
        for (int mi = 0; mi < 2; mi++) {
            int R = wm*32 + mi*16;
            *(uint4*)&ar0[mi][0] = *(uint4*)&As[(R+g  )*GPAD + t*8];
            *(uint4*)&ar0[mi][4] = *(uint4*)&As[(R+g  )*GPAD + t*8 + 4];
            *(uint4*)&ar8[mi][0] = *(uint4*)&As[(R+g+8)*GPAD + t*8];
            *(uint4*)&ar8[mi][4] = *(uint4*)&As[(R+g+8)*GPAD + t*8 + 4];
        }
#pragma unroll
        for (int ni = 0; ni < 8; ni++) {
            uint32_t bsp[8];
            int NR = wn*64 + ni*8 + g;
            *(uint4*)&bsp[0] = *(uint4*)&Ws[NR*GPAD + t*8];
            *(uint4*)&bsp[4] = *(uint4*)&Ws[NR*GPAD + t*8 + 4];
#pragma unroll
            for (int c2 = 0; c2 < 4; c2++) {
                mma_tf32(acc[0][ni], ar0[0][2*c2], ar8[0][2*c2],
                         ar0[0][2*c2+1], ar8[0][2*c2+1], bsp[2*c2], bsp[2*c2+1]);
                mma_tf32(acc[1][ni], ar0[1][2*c2], ar8[1][2*c2],
                         ar0[1][2*c2+1], ar8[1][2*c2+1], bsp[2*c2], bsp[2*c2+1]);
            }
        }
        __syncthreads();
    }

#pragma unroll
    for (int ni = 0; ni < 8; ni++) {
        int ncl = wn*64 + ni*8 + 2*t;
        float2 bv = *(const float2*)(bias + ncl);
#pragma unroll
        for (int mi = 0; mi < 2; mi++) {
            float4 cf = acc[mi][ni];
            int r0 = m0 + wm*32 + mi*16 + g;
            float2 o0 = { cf.x + bv.x, cf.y + bv.y };
            float2 o1 = { cf.z + bv.x, cf.w + bv.y };
            *(float2*)(Z + (size_t)r0*1024 + n0 + ncl)     = o0;
            *(float2*)(Z + (size_t)(r0+8)*1024 + n0 + ncl) = o1;
        }
    }
}

// ---------------- recurrence: one CTA per (cell, batch) — round-4 proven -----
#define RSMEM (65536 + 512 + 2048)

template<int LAYER>
__global__ void __launch_bounds__(512, 1) recur_kernel(
    const float* __restrict__ whhf, const float* __restrict__ whhb)
{
    extern __shared__ char smraw[];
    u64*   wsm = (u64*)smraw;                       // [16 kp][512 j]
    float* hs  = (float*)(smraw + 65536);           // [128]
    float* zs  = (float*)(smraw + 65536 + 512);     // [512]

    const int tid  = threadIdx.x;                   // = j (Whh row)
    const int cell = blockIdx.x >> 6;
    const int b    = blockIdx.x & 63;
    const float* whh = cell ? whhb : whhf;
    const float* zx  = LAYER ? g_zx1 : g_zx0;
    float*       ys  = LAYER ? g_ys1 : g_ys0;

    const u64* wrow = (const u64*)whh + (size_t)tid*64;
    u64 wreg[48];
#pragma unroll
    for (int q = 0; q < 48; q++) wreg[q] = __ldg(wrow + q);
#pragma unroll
    for (int q = 0; q < 16; q++) wsm[q*512 + tid] = __ldg(wrow + 48 + q);

    if (tid < 128) hs[tid] = 0.f;

    uint32_t hs_s  = (uint32_t)__cvta_generic_to_shared(hs);
    uint32_t wsm_s = (uint32_t)__cvta_generic_to_shared(wsm);

    const float* zptr = zx + (size_t)b*1024 + cell*512 + tid;
    float* ysp = ys + (size_t)b*256 + cell*128 + tid;
    float zcur = __ldcs(zptr);
    float c = 0.f;

    __syncthreads();

    for (int t = 0; t < SEQ; t++) {
        float znext = __ldcs(zptr + (size_t)(t+1)*65536);

        u64 acc0 = 0ull, acc1 = 0ull;
#pragma unroll
        for (int q = 0; q < 48; q += 2) {
            u64 ha, hb;
            lds2(ha, hb, hs_s + q*8);
            ffma2(acc0, wreg[q],   ha);
            ffma2(acc1, wreg[q+1], hb);
        }
#pragma unroll
        for (int kp = 0; kp < 16; kp += 2) {
            u64 ha, hb;
            lds2(ha, hb, hs_s + 384 + kp*8);
            u64 wa = lds1(wsm_s + (kp*512     + tid)*8);
            u64 wb = lds1(wsm_s + ((kp+1)*512 + tid)*8);
            ffma2(acc0, wa, ha);
            ffma2(acc1, wb, hb);
        }
        float x0,x1,x2,x3;
        unpk(x0,x1,acc0); unpk(x2,x3,acc1);
        zs[tid] = ((x0+x1)+(x2+x3)) + zcur;
        zcur = znext;
        __syncthreads();

        if (tid < 128) {
            float zi = zs[tid], zf = zs[128+tid], zg = zs[256+tid], zo = zs[384+tid];
            float ig = sigm(zi), fg = sigm(zf), gg = tanh_s(zg), og = sigm(zo);
            c = fg*c + ig*gg;
            float h = og * tanh_s(c);
            hs[tid] = h;
            ysp[(size_t)t*16384] = h;
        }
        __syncthreads();
    }
}

// ---------------- final FC + sigmoid ----------------------------------------
__global__ void __launch_bounds__(256) fc_kernel(
    const float* __restrict__ fcw, const float* __restrict__ fcb,
    float* __restrict__ out)
{
    int gtid = blockIdx.x*blockDim.x + threadIdx.x;
    int row = gtid >> 5, lane = gtid & 31;
    if (row >= NROWS) return;
    const float* y = g_ys1 + (size_t)row*256;
    float s = 0.f;
#pragma unroll
    for (int i = 0; i < 8; i++) s += y[lane + i*32] * __ldg(fcw + lane + i*32);
#pragma unroll
    for (int o = 16; o; o >>= 1) s += __shfl_xor_sync(0xffffffffu, s, o);
    if (lane == 0) out[row] = 1.f/(1.f + __expf(-(s + fcb[0])));
}

// ---------------- launch -----------------------------------------------------
extern "C" void kernel_launch(void* const* d_in, const int* in_sizes, int n_in,
                              void* d_out, int out_size)
{
    const float* x     = (const float*)d_in[0];
    const float* wih0f = (const float*)d_in[1];
    const float* whh0f = (const float*)d_in[2];
    const float* b0f   = (const float*)d_in[3];
    const float* wih0b = (const float*)d_in[4];
    const float* whh0b = (const float*)d_in[5];
    const float* b0b   = (const float*)d_in[6];
    const float* wih1f = (const float*)d_in[7];
    const float* whh1f = (const float*)d_in[8];
    const float* b1f   = (const float*)d_in[9];
    const float* wih1b = (const float*)d_in[10];
    const float* whh1b = (const float*)d_in[11];
    const float* b1b   = (const float*)d_in[12];
    const float* fcw   = (const float*)d_in[13];
    const float* fcb   = (const float*)d_in[14];
    float* out = (float*)d_out;

    cudaFuncSetAttribute(recur_kernel<0>, cudaFuncAttributeMaxDynamicSharedMemorySize, RSMEM);
    cudaFuncSetAttribute(recur_kernel<1>, cudaFuncAttributeMaxDynamicSharedMemorySize, RSMEM);

    dim3 ggrid(8, NROWS/128);
    mma_gemm<DIM, 0><<<ggrid, 256>>>(x, wih0f, wih0b, b0f, b0b);
    recur_kernel<0><<<128, 512, RSMEM>>>(whh0f, whh0b);

    mma_gemm<256, 1><<<ggrid, 256>>>(nullptr, wih1f, wih1b, b1f, b1b);
    recur_kernel<1><<<128, 512, RSMEM>>>(whh1f, whh1b);

    fc_kernel<<<(NROWS*32)/256, 256>>>(fcw, fcb, out);
}